// round 1
// baseline (speedup 1.0000x reference)
#include <cuda_runtime.h>
#include <math.h>

// Problem constants
#define BB   2
#define SS   2048
#define DD   2048
#define HQ   16
#define HKV  4
#define HD   128
#define KVD  512          // HKV*HD
#define MM   (BB*SS)      // 4096

// Scratch (device globals: allocation-free contract)
__device__ float g_Q[(size_t)MM * DD];   // [4096, 2048]
__device__ float g_K[(size_t)MM * KVD];  // [4096, 512]
__device__ float g_V[(size_t)MM * KVD];  // [4096, 512]

// ---------------------------------------------------------------------------
// Tiled fp32 GEMM + bias: Y[M,N] = X[M,K] @ W[K,N] + b[N]
// 128x128 block tile, BK=16, 256 threads, 8x8 micro-tile per thread.
// blockIdx.z selects (W0,b0,Y0) or (W1,b1,Y1) so K and V fuse into one launch.
// ---------------------------------------------------------------------------
__global__ __launch_bounds__(256) void gemm_bias2(
    const float* __restrict__ X,
    const float* __restrict__ W0, const float* __restrict__ b0, float* __restrict__ Y0,
    const float* __restrict__ W1, const float* __restrict__ b1, float* __restrict__ Y1,
    int M, int N, int Kdim)
{
    const float* __restrict__ W  = blockIdx.z ? W1 : W0;
    const float* __restrict__ bi = blockIdx.z ? b1 : b0;
    float*       __restrict__ Y  = blockIdx.z ? Y1 : Y0;

    __shared__ __align__(16) float As[16][128];  // As[k][m]
    __shared__ __align__(16) float Bs[16][128];  // Bs[k][n]

    const int tid = threadIdx.x;
    const int tx = tid & 15;          // 0..15 (column group)
    const int ty = tid >> 4;          // 0..15 (row group)
    const int bm = blockIdx.y * 128;
    const int bn = blockIdx.x * 128;

    float acc[8][8];
    #pragma unroll
    for (int i = 0; i < 8; i++)
        #pragma unroll
        for (int j = 0; j < 8; j++) acc[i][j] = 0.f;

    for (int k0 = 0; k0 < Kdim; k0 += 16) {
        // Load X tile (128 rows x 16 cols) -> As[k][m]
        #pragma unroll
        for (int it = 0; it < 2; it++) {
            int f  = tid + it * 256;          // 0..511
            int m  = f >> 2;                  // 0..127
            int kq = (f & 3) * 4;             // 0,4,8,12
            float4 v = *(const float4*)(X + (size_t)(bm + m) * Kdim + k0 + kq);
            As[kq + 0][m] = v.x;
            As[kq + 1][m] = v.y;
            As[kq + 2][m] = v.z;
            As[kq + 3][m] = v.w;
        }
        // Load W tile (16 rows x 128 cols) -> Bs[k][n]
        #pragma unroll
        for (int it = 0; it < 2; it++) {
            int f  = tid + it * 256;
            int kk = f >> 5;                  // 0..15
            int nq = (f & 31) * 4;            // 0..124
            *(float4*)&Bs[kk][nq] =
                *(const float4*)(W + (size_t)(k0 + kk) * N + bn + nq);
        }
        __syncthreads();

        #pragma unroll
        for (int kk = 0; kk < 16; kk++) {
            float a[8], b[8];
            *(float4*)&a[0] = *(const float4*)&As[kk][ty * 8];
            *(float4*)&a[4] = *(const float4*)&As[kk][ty * 8 + 4];
            *(float4*)&b[0] = *(const float4*)&Bs[kk][tx * 4];        // cols tx*4..+3
            *(float4*)&b[4] = *(const float4*)&Bs[kk][64 + tx * 4];   // cols 64+tx*4..+3
            #pragma unroll
            for (int i = 0; i < 8; i++)
                #pragma unroll
                for (int j = 0; j < 8; j++)
                    acc[i][j] = fmaf(a[i], b[j], acc[i][j]);
        }
        __syncthreads();
    }

    // Epilogue with bias; column mapping matches fragment mapping
    #pragma unroll
    for (int i = 0; i < 8; i++) {
        int m = bm + ty * 8 + i;
        int n0 = bn + tx * 4;
        int n1 = bn + 64 + tx * 4;
        float4 o0, o1;
        o0.x = acc[i][0] + bi[n0 + 0];
        o0.y = acc[i][1] + bi[n0 + 1];
        o0.z = acc[i][2] + bi[n0 + 2];
        o0.w = acc[i][3] + bi[n0 + 3];
        o1.x = acc[i][4] + bi[n1 + 0];
        o1.y = acc[i][5] + bi[n1 + 1];
        o1.z = acc[i][6] + bi[n1 + 2];
        o1.w = acc[i][7] + bi[n1 + 3];
        *(float4*)(Y + (size_t)m * N + n0) = o0;
        *(float4*)(Y + (size_t)m * N + n1) = o1;
    }
}

// ---------------------------------------------------------------------------
// Flash-attention (fp32, online softmax).
// Grid: (S/64, HQ, B). Block: 256 threads (16x16).
// Each block: 64 queries x full 2048 keys for one (b, head).
// SMEM: Qs[d][q] 32KB, Ks[d][k] 32KB, Vs[k][d] 32KB, Ps[q][k] 16KB = 112KB.
// ---------------------------------------------------------------------------
#define ATTN_SMEM_BYTES ((128*64 + 128*64 + 64*128 + 64*64) * 4)

__global__ __launch_bounds__(256) void attn_kernel(
    const float* __restrict__ Q, const float* __restrict__ K,
    const float* __restrict__ V, float* __restrict__ O)
{
    extern __shared__ __align__(16) float sm[];
    float* Qs = sm;                    // [128][64]  d-major
    float* Ks = sm + 128 * 64;         // [128][64]  d-major
    float* Vs = sm + 2 * 128 * 64;     // [64][128]  k-major
    float* Ps = sm + 3 * 128 * 64;     // [64][64]

    const int tid = threadIdx.x;
    const int tx = tid & 15;           // key-col group / hd-col group
    const int ty = tid >> 4;           // query-row group
    const int q0 = blockIdx.x * 64;
    const int h  = blockIdx.y;
    const int b  = blockIdx.z;
    const int g  = h & (HKV - 1);      // kv head = h % 4
    const float scale = 0.08838834764831845f;  // 1/sqrt(128)

    const float* Qb = Q + (size_t)b * SS * DD  + (size_t)h * HD;
    const float* Kb = K + (size_t)b * SS * KVD + (size_t)g * HD;
    const float* Vb = V + (size_t)b * SS * KVD + (size_t)g * HD;

    // Load Q tile transposed (pre-scaled). Lane-consecutive q -> conflict-free stores.
    #pragma unroll
    for (int it = 0; it < 8; it++) {
        int f  = tid + it * 256;          // 0..2047
        int qq = f & 63;
        int d4 = (f >> 6) * 4;
        float4 v = *(const float4*)(Qb + (size_t)(q0 + qq) * DD + d4);
        Qs[(d4 + 0) * 64 + qq] = v.x * scale;
        Qs[(d4 + 1) * 64 + qq] = v.y * scale;
        Qs[(d4 + 2) * 64 + qq] = v.z * scale;
        Qs[(d4 + 3) * 64 + qq] = v.w * scale;
    }

    float m_i[4], l_i[4], o[4][8];
    #pragma unroll
    for (int i = 0; i < 4; i++) {
        m_i[i] = -INFINITY;
        l_i[i] = 0.f;
        #pragma unroll
        for (int j = 0; j < 8; j++) o[i][j] = 0.f;
    }

    for (int kt = 0; kt < SS / 64; kt++) {
        const int k0 = kt * 64;
        // K tile transposed
        #pragma unroll
        for (int it = 0; it < 8; it++) {
            int f  = tid + it * 256;
            int kc = f & 63;
            int d4 = (f >> 6) * 4;
            float4 v = *(const float4*)(Kb + (size_t)(k0 + kc) * KVD + d4);
            Ks[(d4 + 0) * 64 + kc] = v.x;
            Ks[(d4 + 1) * 64 + kc] = v.y;
            Ks[(d4 + 2) * 64 + kc] = v.z;
            Ks[(d4 + 3) * 64 + kc] = v.w;
        }
        // V tile natural layout (coalesced)
        #pragma unroll
        for (int it = 0; it < 8; it++) {
            int f  = tid + it * 256;
            int kc = f >> 5;
            int d4 = (f & 31) * 4;
            *(float4*)(Vs + kc * 128 + d4) =
                *(const float4*)(Vb + (size_t)(k0 + kc) * KVD + d4);
        }
        __syncthreads();

        // Scores: s[i][j] = q(ty*4+i) . k(tx*4+j)
        float s[4][4];
        #pragma unroll
        for (int i = 0; i < 4; i++)
            #pragma unroll
            for (int j = 0; j < 4; j++) s[i][j] = 0.f;

        #pragma unroll 8
        for (int d = 0; d < 128; d++) {
            float4 qf = *(const float4*)(Qs + d * 64 + ty * 4);
            float4 kf = *(const float4*)(Ks + d * 64 + tx * 4);
            const float qa[4] = {qf.x, qf.y, qf.z, qf.w};
            const float ka[4] = {kf.x, kf.y, kf.z, kf.w};
            #pragma unroll
            for (int i = 0; i < 4; i++)
                #pragma unroll
                for (int j = 0; j < 4; j++)
                    s[i][j] = fmaf(qa[i], ka[j], s[i][j]);
        }

        // Online softmax per query row (row stats reduced over the 16 tx lanes)
        #pragma unroll
        for (int i = 0; i < 4; i++) {
            float tm = fmaxf(fmaxf(s[i][0], s[i][1]), fmaxf(s[i][2], s[i][3]));
            #pragma unroll
            for (int off = 8; off >= 1; off >>= 1)
                tm = fmaxf(tm, __shfl_xor_sync(0xffffffffu, tm, off));
            float mn = fmaxf(m_i[i], tm);
            float alpha = __expf(m_i[i] - mn);
            float rs = 0.f;
            #pragma unroll
            for (int j = 0; j < 4; j++) {
                float p = __expf(s[i][j] - mn);
                s[i][j] = p;
                rs += p;
            }
            #pragma unroll
            for (int off = 8; off >= 1; off >>= 1)
                rs += __shfl_xor_sync(0xffffffffu, rs, off);
            l_i[i] = l_i[i] * alpha + rs;
            m_i[i] = mn;
            #pragma unroll
            for (int j = 0; j < 8; j++) o[i][j] *= alpha;
            *(float4*)(Ps + (ty * 4 + i) * 64 + tx * 4) =
                make_float4(s[i][0], s[i][1], s[i][2], s[i][3]);
        }
        __syncthreads();

        // O += P @ V  (hd columns tx*4..+3 and 64+tx*4..+3)
        #pragma unroll 8
        for (int kk = 0; kk < 64; kk++) {
            float p0 = Ps[(ty * 4 + 0) * 64 + kk];
            float p1 = Ps[(ty * 4 + 1) * 64 + kk];
            float p2 = Ps[(ty * 4 + 2) * 64 + kk];
            float p3 = Ps[(ty * 4 + 3) * 64 + kk];
            float4 v0 = *(const float4*)(Vs + kk * 128 + tx * 4);
            float4 v1 = *(const float4*)(Vs + kk * 128 + 64 + tx * 4);
            const float va0[4] = {v0.x, v0.y, v0.z, v0.w};
            const float va1[4] = {v1.x, v1.y, v1.z, v1.w};
            const float pa[4] = {p0, p1, p2, p3};
            #pragma unroll
            for (int i = 0; i < 4; i++) {
                #pragma unroll
                for (int j = 0; j < 4; j++) {
                    o[i][j]     = fmaf(pa[i], va0[j], o[i][j]);
                    o[i][4 + j] = fmaf(pa[i], va1[j], o[i][4 + j]);
                }
            }
        }
        __syncthreads();
    }

    // Epilogue: O / l, write [B,S,HQ*HD]
    float* Ob = O + (size_t)b * SS * DD + (size_t)h * HD;
    #pragma unroll
    for (int i = 0; i < 4; i++) {
        float inv = 1.f / l_i[i];
        int row = q0 + ty * 4 + i;
        float4 o0 = make_float4(o[i][0] * inv, o[i][1] * inv, o[i][2] * inv, o[i][3] * inv);
        float4 o1 = make_float4(o[i][4] * inv, o[i][5] * inv, o[i][6] * inv, o[i][7] * inv);
        *(float4*)(Ob + (size_t)row * DD + tx * 4)      = o0;
        *(float4*)(Ob + (size_t)row * DD + 64 + tx * 4) = o1;
    }
}

// ---------------------------------------------------------------------------
extern "C" void kernel_launch(void* const* d_in, const int* in_sizes, int n_in,
                              void* d_out, int out_size)
{
    (void)in_sizes; (void)n_in; (void)out_size;
    const float* H  = (const float*)d_in[0];
    const float* Wq = (const float*)d_in[1];
    const float* bq = (const float*)d_in[2];
    const float* Wk = (const float*)d_in[3];
    const float* bk = (const float*)d_in[4];
    const float* Wv = (const float*)d_in[5];
    const float* bv = (const float*)d_in[6];
    float* out = (float*)d_out;

    float *Qp, *Kp, *Vp;
    cudaGetSymbolAddress((void**)&Qp, g_Q);
    cudaGetSymbolAddress((void**)&Kp, g_K);
    cudaGetSymbolAddress((void**)&Vp, g_V);

    dim3 blk(256);
    // Q projection: N=2048
    gemm_bias2<<<dim3(DD / 128, MM / 128, 1), blk>>>(
        H, Wq, bq, Qp, Wq, bq, Qp, MM, DD, DD);
    // K and V projections fused via z: N=512
    gemm_bias2<<<dim3(KVD / 128, MM / 128, 2), blk>>>(
        H, Wk, bk, Kp, Wv, bv, Vp, MM, KVD, DD);

    cudaFuncSetAttribute(attn_kernel,
                         cudaFuncAttributeMaxDynamicSharedMemorySize,
                         ATTN_SMEM_BYTES);
    attn_kernel<<<dim3(SS / 64, HQ, BB), blk, ATTN_SMEM_BYTES>>>(Qp, Kp, Vp, out);
}

// round 2
// speedup vs baseline: 3.1816x; 3.1816x over previous
#include <cuda_runtime.h>
#include <math.h>

#define BB   2
#define SS   2048
#define DD   2048
#define HQ   16
#define HKV  4
#define HD   128
#define KVD  512
#define MM   (BB*SS)

__device__ float g_Q[(size_t)MM * DD];
__device__ float g_K[(size_t)MM * KVD];
__device__ float g_V[(size_t)MM * KVD];

__device__ __forceinline__ unsigned f2tf(float x) {
    unsigned r;
    asm("cvt.rna.tf32.f32 %0, %1;" : "=r"(r) : "f"(x));
    return r;
}

__device__ __forceinline__ void mma_tf32(float c[4], const unsigned a[4], const unsigned b[2]) {
    asm volatile(
        "mma.sync.aligned.m16n8k8.row.col.f32.tf32.tf32.f32 "
        "{%0,%1,%2,%3},{%4,%5,%6,%7},{%8,%9},{%0,%1,%2,%3};"
        : "+f"(c[0]), "+f"(c[1]), "+f"(c[2]), "+f"(c[3])
        : "r"(a[0]), "r"(a[1]), "r"(a[2]), "r"(a[3]), "r"(b[0]), "r"(b[1]));
}

// ---------------------------------------------------------------------------
// tf32 GEMM + bias: Y = X@W + b. 128x128x32 tiles, 8 warps (2m x 4n).
// As[m][k] stride 36 (bank = 4m+k -> == lane for fragments, conflict-free).
// Bs[k][n] stride 136 (bank = 8k+n -> conflict-free).
// blockIdx.z fuses two (W,b,Y) problems (K and V projections).
// ---------------------------------------------------------------------------
__global__ __launch_bounds__(256, 2) void gemm_tf32(
    const float* __restrict__ X,
    const float* __restrict__ W0, const float* __restrict__ b0, float* __restrict__ Y0,
    const float* __restrict__ W1, const float* __restrict__ b1, float* __restrict__ Y1,
    int M, int N, int Kdim)
{
    const float* __restrict__ W  = blockIdx.z ? W1 : W0;
    const float* __restrict__ bi = blockIdx.z ? b1 : b0;
    float*       __restrict__ Y  = blockIdx.z ? Y1 : Y0;

    __shared__ unsigned As[128 * 36];
    __shared__ unsigned Bs[32 * 136];

    const int tid  = threadIdx.x;
    const int lane = tid & 31;
    const int wid  = tid >> 5;
    const int wm   = wid & 1;     // 0..1
    const int wn   = wid >> 1;    // 0..3
    const int lr   = lane >> 2;   // 0..7
    const int lc   = lane & 3;    // 0..3
    const int bm = blockIdx.y * 128;
    const int bn = blockIdx.x * 128;

    float acc[4][4][4];
    #pragma unroll
    for (int i = 0; i < 4; i++)
        #pragma unroll
        for (int j = 0; j < 4; j++)
            #pragma unroll
            for (int k = 0; k < 4; k++) acc[i][j][k] = 0.f;

    for (int k0 = 0; k0 < Kdim; k0 += 32) {
        #pragma unroll
        for (int it = 0; it < 4; it++) {
            int f = tid + it * 256;
            // X tile 128x32 (coalesced 4-row blocks per warp)
            int m  = f >> 3;
            int kq = (f & 7) * 4;
            float4 v = *(const float4*)(X + (size_t)(bm + m) * Kdim + k0 + kq);
            *(uint4*)&As[m * 36 + kq] =
                make_uint4(f2tf(v.x), f2tf(v.y), f2tf(v.z), f2tf(v.w));
            // W tile 32x128 (coalesced rows)
            int kk = f >> 5;
            int nq = (f & 31) * 4;
            float4 w = *(const float4*)(W + (size_t)(k0 + kk) * N + bn + nq);
            *(uint4*)&Bs[kk * 136 + nq] =
                make_uint4(f2tf(w.x), f2tf(w.y), f2tf(w.z), f2tf(w.w));
        }
        __syncthreads();

        #pragma unroll
        for (int s = 0; s < 4; s++) {
            const int c = s * 8 + lc;
            unsigned af[4][4], bf[4][2];
            #pragma unroll
            for (int mt = 0; mt < 4; mt++) {
                int r = wm * 64 + mt * 16 + lr;
                af[mt][0] = As[r * 36 + c];
                af[mt][1] = As[(r + 8) * 36 + c];
                af[mt][2] = As[r * 36 + c + 4];
                af[mt][3] = As[(r + 8) * 36 + c + 4];
            }
            #pragma unroll
            for (int nt = 0; nt < 4; nt++) {
                int n = wn * 32 + nt * 8 + lr;
                bf[nt][0] = Bs[c * 136 + n];
                bf[nt][1] = Bs[(c + 4) * 136 + n];
            }
            #pragma unroll
            for (int mt = 0; mt < 4; mt++)
                #pragma unroll
                for (int nt = 0; nt < 4; nt++)
                    mma_tf32(acc[mt][nt], af[mt], bf[nt]);
        }
        __syncthreads();
    }

    #pragma unroll
    for (int mt = 0; mt < 4; mt++) {
        int r = bm + wm * 64 + mt * 16 + lr;
        #pragma unroll
        for (int nt = 0; nt < 4; nt++) {
            int cc = bn + wn * 32 + nt * 8 + 2 * lc;
            float bv0 = bi[cc], bv1 = bi[cc + 1];
            *(float2*)(Y + (size_t)r * N + cc) =
                make_float2(acc[mt][nt][0] + bv0, acc[mt][nt][1] + bv1);
            *(float2*)(Y + (size_t)(r + 8) * N + cc) =
                make_float2(acc[mt][nt][2] + bv0, acc[mt][nt][3] + bv1);
        }
    }
}

// ---------------------------------------------------------------------------
// tf32 flash attention. CTA = 128 q-rows; 8 warps: mw=wid>>1 (32-row group),
// nw=wid&1 (key/HD column split). Key tile = 64. All operand tiles stored
// natural-layout with pad strides chosen for conflict-free fragment LDS.
//   Qs[q][d]   stride 132  (a-frag bank = 4q+d == lane)
//   Ks[key][d] stride 132  (b-frag bank = 4key+d == lane)
//   Vs[key][d] stride 136  (b-frag bank = 8key+d, bijective)
//   Ps[q][key] stride 68   (a-frag bank = 4q+key == lane)
// Row stats (m,l) kept redundantly in registers; cross-warp partials via SMEM.
// ---------------------------------------------------------------------------
#define ATTN_SMEM_FLOATS (128*132 + 64*132 + 64*136 + 128*68 + 256 + 256)

__global__ __launch_bounds__(256) void attn_tf32(
    const float* __restrict__ Q, const float* __restrict__ K,
    const float* __restrict__ V, float* __restrict__ O)
{
    extern __shared__ float sm[];
    unsigned* Qs = (unsigned*)sm;                               // 128*132
    unsigned* Ks = (unsigned*)(sm + 128 * 132);                 // 64*132
    unsigned* Vs = (unsigned*)(sm + 128 * 132 + 64 * 132);      // 64*136
    unsigned* Ps = (unsigned*)(sm + 128 * 132 + 64 * 132 + 64 * 136); // 128*68
    float* pmax = sm + 128 * 132 + 64 * 132 + 64 * 136 + 128 * 68;    // [2][128]
    float* psum = pmax + 256;                                          // [2][128]

    const int tid  = threadIdx.x;
    const int lane = tid & 31;
    const int wid  = tid >> 5;
    const int mw = wid >> 1;   // 0..3
    const int nw = wid & 1;    // 0..1
    const int lr = lane >> 2;  // 0..7
    const int lc = lane & 3;   // 0..3
    const int q0 = blockIdx.x * 128;
    const int h  = blockIdx.y;
    const int b  = blockIdx.z;
    const int g  = h & (HKV - 1);
    const float scale = 0.08838834764831845f;  // 1/sqrt(128)

    const float* Qb = Q + (size_t)b * SS * DD  + (size_t)h * HD;
    const float* Kb = K + (size_t)b * SS * KVD + (size_t)g * HD;
    const float* Vb = V + (size_t)b * SS * KVD + (size_t)g * HD;

    // Q tile 128x128 -> SMEM (pre-scaled, tf32)
    #pragma unroll
    for (int it = 0; it < 16; it++) {
        int f  = tid + it * 256;
        int q  = f >> 5;
        int dq = (f & 31) * 4;
        float4 v = *(const float4*)(Qb + (size_t)(q0 + q) * DD + dq);
        *(uint4*)&Qs[q * 132 + dq] = make_uint4(
            f2tf(v.x * scale), f2tf(v.y * scale), f2tf(v.z * scale), f2tf(v.w * scale));
    }

    float o[2][8][4];
    float rm[2][2], rl[2][2];
    #pragma unroll
    for (int mt = 0; mt < 2; mt++) {
        rm[mt][0] = -INFINITY; rm[mt][1] = -INFINITY;
        rl[mt][0] = 0.f;       rl[mt][1] = 0.f;
        #pragma unroll
        for (int nt = 0; nt < 8; nt++)
            #pragma unroll
            for (int k = 0; k < 4; k++) o[mt][nt][k] = 0.f;
    }

    for (int kt = 0; kt < SS / 64; kt++) {
        const int k0 = kt * 64;
        __syncthreads();   // prev PV done reading Ks/Vs (and Qs ready on kt=0)
        #pragma unroll
        for (int it = 0; it < 8; it++) {
            int f   = tid + it * 256;
            int key = f >> 5;
            int dq  = (f & 31) * 4;
            float4 kv = *(const float4*)(Kb + (size_t)(k0 + key) * KVD + dq);
            *(uint4*)&Ks[key * 132 + dq] =
                make_uint4(f2tf(kv.x), f2tf(kv.y), f2tf(kv.z), f2tf(kv.w));
            float4 vv = *(const float4*)(Vb + (size_t)(k0 + key) * KVD + dq);
            *(uint4*)&Vs[key * 136 + dq] =
                make_uint4(f2tf(vv.x), f2tf(vv.y), f2tf(vv.z), f2tf(vv.w));
        }
        __syncthreads();

        // S = Q K^T : this warp -> rows 32*mw..+32, keys 32*nw..+32
        float sacc[2][4][4];
        #pragma unroll
        for (int mt = 0; mt < 2; mt++)
            #pragma unroll
            for (int nt = 0; nt < 4; nt++)
                #pragma unroll
                for (int k = 0; k < 4; k++) sacc[mt][nt][k] = 0.f;

        #pragma unroll
        for (int st = 0; st < 16; st++) {
            const int c = st * 8 + lc;
            unsigned af[2][4], bf[4][2];
            #pragma unroll
            for (int mt = 0; mt < 2; mt++) {
                int r = 32 * mw + 16 * mt + lr;
                af[mt][0] = Qs[r * 132 + c];
                af[mt][1] = Qs[(r + 8) * 132 + c];
                af[mt][2] = Qs[r * 132 + c + 4];
                af[mt][3] = Qs[(r + 8) * 132 + c + 4];
            }
            #pragma unroll
            for (int nt = 0; nt < 4; nt++) {
                int n = 32 * nw + 8 * nt + lr;
                bf[nt][0] = Ks[n * 132 + c];
                bf[nt][1] = Ks[n * 132 + c + 4];
            }
            #pragma unroll
            for (int mt = 0; mt < 2; mt++)
                #pragma unroll
                for (int nt = 0; nt < 4; nt++)
                    mma_tf32(sacc[mt][nt], af[mt], bf[nt]);
        }

        // warp-local row max over this warp's 32-key slice
        #pragma unroll
        for (int mt = 0; mt < 2; mt++) {
            float m0 = sacc[mt][0][0], m1 = sacc[mt][0][2];
            #pragma unroll
            for (int nt = 0; nt < 4; nt++) {
                m0 = fmaxf(m0, fmaxf(sacc[mt][nt][0], sacc[mt][nt][1]));
                m1 = fmaxf(m1, fmaxf(sacc[mt][nt][2], sacc[mt][nt][3]));
            }
            m0 = fmaxf(m0, __shfl_xor_sync(0xffffffffu, m0, 1));
            m0 = fmaxf(m0, __shfl_xor_sync(0xffffffffu, m0, 2));
            m1 = fmaxf(m1, __shfl_xor_sync(0xffffffffu, m1, 1));
            m1 = fmaxf(m1, __shfl_xor_sync(0xffffffffu, m1, 2));
            if (lc == 0) {
                int r = 32 * mw + 16 * mt + lr;
                pmax[nw * 128 + r]     = m0;
                pmax[nw * 128 + r + 8] = m1;
            }
        }
        __syncthreads();

        // combine maxima, exponentiate, write P, partial row sums
        float mnew[2][2], alpha[2][2], psv[2][2];
        #pragma unroll
        for (int mt = 0; mt < 2; mt++)
            #pragma unroll
            for (int hh = 0; hh < 2; hh++) {
                int r = 32 * mw + 16 * mt + lr + 8 * hh;
                float mn = fmaxf(pmax[r], pmax[128 + r]);
                mn = fmaxf(mn, rm[mt][hh]);
                mnew[mt][hh]  = mn;
                alpha[mt][hh] = __expf(rm[mt][hh] - mn);
                psv[mt][hh]   = 0.f;
            }
        #pragma unroll
        for (int mt = 0; mt < 2; mt++) {
            int r = 32 * mw + 16 * mt + lr;
            #pragma unroll
            for (int nt = 0; nt < 4; nt++) {
                float p0 = __expf(sacc[mt][nt][0] - mnew[mt][0]);
                float p1 = __expf(sacc[mt][nt][1] - mnew[mt][0]);
                float p2 = __expf(sacc[mt][nt][2] - mnew[mt][1]);
                float p3 = __expf(sacc[mt][nt][3] - mnew[mt][1]);
                psv[mt][0] += p0 + p1;
                psv[mt][1] += p2 + p3;
                int cc = 32 * nw + 8 * nt + 2 * lc;
                *(uint2*)&Ps[r * 68 + cc]       = make_uint2(f2tf(p0), f2tf(p1));
                *(uint2*)&Ps[(r + 8) * 68 + cc] = make_uint2(f2tf(p2), f2tf(p3));
            }
        }
        #pragma unroll
        for (int mt = 0; mt < 2; mt++)
            #pragma unroll
            for (int hh = 0; hh < 2; hh++) {
                float v = psv[mt][hh];
                v += __shfl_xor_sync(0xffffffffu, v, 1);
                v += __shfl_xor_sync(0xffffffffu, v, 2);
                psv[mt][hh] = v;
            }
        if (lc == 0) {
            #pragma unroll
            for (int mt = 0; mt < 2; mt++)
                #pragma unroll
                for (int hh = 0; hh < 2; hh++) {
                    int r = 32 * mw + 16 * mt + lr + 8 * hh;
                    psum[nw * 128 + r] = psv[mt][hh];
                }
        }
        __syncthreads();

        // update row stats (redundant per warp, identical values) + rescale O
        #pragma unroll
        for (int mt = 0; mt < 2; mt++)
            #pragma unroll
            for (int hh = 0; hh < 2; hh++) {
                int r = 32 * mw + 16 * mt + lr + 8 * hh;
                rl[mt][hh] = rl[mt][hh] * alpha[mt][hh] + psum[r] + psum[128 + r];
                rm[mt][hh] = mnew[mt][hh];
            }
        #pragma unroll
        for (int mt = 0; mt < 2; mt++)
            #pragma unroll
            for (int nt = 0; nt < 8; nt++) {
                o[mt][nt][0] *= alpha[mt][0];
                o[mt][nt][1] *= alpha[mt][0];
                o[mt][nt][2] *= alpha[mt][1];
                o[mt][nt][3] *= alpha[mt][1];
            }

        // O += P V : this warp -> rows 32*mw..+32, HD cols 64*nw..+64
        #pragma unroll
        for (int st = 0; st < 8; st++) {
            const int kk = st * 8 + lc;
            unsigned af[2][4], bf[8][2];
            #pragma unroll
            for (int mt = 0; mt < 2; mt++) {
                int r = 32 * mw + 16 * mt + lr;
                af[mt][0] = Ps[r * 68 + kk];
                af[mt][1] = Ps[(r + 8) * 68 + kk];
                af[mt][2] = Ps[r * 68 + kk + 4];
                af[mt][3] = Ps[(r + 8) * 68 + kk + 4];
            }
            #pragma unroll
            for (int nt = 0; nt < 8; nt++) {
                int n = 64 * nw + 8 * nt + lr;
                bf[nt][0] = Vs[kk * 136 + n];
                bf[nt][1] = Vs[(kk + 4) * 136 + n];
            }
            #pragma unroll
            for (int mt = 0; mt < 2; mt++)
                #pragma unroll
                for (int nt = 0; nt < 8; nt++)
                    mma_tf32(o[mt][nt], af[mt], bf[nt]);
        }
    }

    // epilogue: normalize and write [B,S,HQ*HD]
    float* Ob = O + (size_t)b * SS * DD + (size_t)h * HD;
    #pragma unroll
    for (int mt = 0; mt < 2; mt++) {
        float inv0 = 1.f / rl[mt][0];
        float inv1 = 1.f / rl[mt][1];
        int r = q0 + 32 * mw + 16 * mt + lr;
        #pragma unroll
        for (int nt = 0; nt < 8; nt++) {
            int cc = 64 * nw + 8 * nt + 2 * lc;
            *(float2*)(Ob + (size_t)r * DD + cc) =
                make_float2(o[mt][nt][0] * inv0, o[mt][nt][1] * inv0);
            *(float2*)(Ob + (size_t)(r + 8) * DD + cc) =
                make_float2(o[mt][nt][2] * inv1, o[mt][nt][3] * inv1);
        }
    }
}

// ---------------------------------------------------------------------------
extern "C" void kernel_launch(void* const* d_in, const int* in_sizes, int n_in,
                              void* d_out, int out_size)
{
    (void)in_sizes; (void)n_in; (void)out_size;
    const float* H  = (const float*)d_in[0];
    const float* Wq = (const float*)d_in[1];
    const float* bq = (const float*)d_in[2];
    const float* Wk = (const float*)d_in[3];
    const float* bk = (const float*)d_in[4];
    const float* Wv = (const float*)d_in[5];
    const float* bv = (const float*)d_in[6];
    float* out = (float*)d_out;

    float *Qp, *Kp, *Vp;
    cudaGetSymbolAddress((void**)&Qp, g_Q);
    cudaGetSymbolAddress((void**)&Kp, g_K);
    cudaGetSymbolAddress((void**)&Vp, g_V);

    dim3 blk(256);
    // Q projection: N=2048
    gemm_tf32<<<dim3(DD / 128, MM / 128, 1), blk>>>(
        H, Wq, bq, Qp, Wq, bq, Qp, MM, DD, DD);
    // K and V projections fused via z: N=512
    gemm_tf32<<<dim3(KVD / 128, MM / 128, 2), blk>>>(
        H, Wk, bk, Kp, Wv, bv, Vp, MM, KVD, DD);

    static int smem_set = 0;
    (void)smem_set;
    cudaFuncSetAttribute(attn_tf32,
                         cudaFuncAttributeMaxDynamicSharedMemorySize,
                         ATTN_SMEM_FLOATS * 4);
    attn_tf32<<<dim3(SS / 128, HQ, BB), blk, ATTN_SMEM_FLOATS * 4>>>(Qp, Kp, Vp, out);
}

// round 3
// speedup vs baseline: 3.3701x; 1.0592x over previous
#include <cuda_runtime.h>
#include <math.h>

#define BB   2
#define SS   2048
#define DD   2048
#define HQ   16
#define HKV  4
#define HD   128
#define KVD  512
#define MM   (BB*SS)
#define NTILE (SS/64)

// Scratch (device globals)
__device__ float g_Q[(size_t)MM * DD];
__device__ float g_K[(size_t)MM * KVD];
__device__ float g_V[(size_t)MM * KVD];
__device__ float g_H[(size_t)MM * DD];
__device__ float g_Wq[(size_t)DD * DD];
__device__ float g_Wk[(size_t)DD * KVD];
__device__ float g_Wv[(size_t)DD * KVD];

__device__ __forceinline__ unsigned f2tf(float x) {
    unsigned r;
    asm("cvt.rna.tf32.f32 %0, %1;" : "=r"(r) : "f"(x));
    return r;
}
__device__ __forceinline__ float f2tff(float x) { return __uint_as_float(f2tf(x)); }

__device__ __forceinline__ void mma_tf32(float c[4], const unsigned a[4], const unsigned b[2]) {
    asm volatile(
        "mma.sync.aligned.m16n8k8.row.col.f32.tf32.tf32.f32 "
        "{%0,%1,%2,%3},{%4,%5,%6,%7},{%8,%9},{%0,%1,%2,%3};"
        : "+f"(c[0]), "+f"(c[1]), "+f"(c[2]), "+f"(c[3])
        : "r"(a[0]), "r"(a[1]), "r"(a[2]), "r"(a[3]), "r"(b[0]), "r"(b[1]));
}

#define CP16(dst, src) \
    asm volatile("cp.async.cg.shared.global [%0], [%1], 16;" :: "r"(dst), "l"(src))
#define CPCOMMIT() asm volatile("cp.async.commit_group;")
#define CPWAIT(N)  asm volatile("cp.async.wait_group %0;" :: "n"(N))

// ---------------------------------------------------------------------------
// Pre-round a tensor to tf32-representable fp32 (one bandwidth pass).
// ---------------------------------------------------------------------------
__global__ void cvt_tf32(float* __restrict__ dst, const float* __restrict__ src, int n4)
{
    int i = blockIdx.x * blockDim.x + threadIdx.x;
    int stride = gridDim.x * blockDim.x;
    for (; i < n4; i += stride) {
        float4 v = ((const float4*)src)[i];
        ((float4*)dst)[i] = make_float4(f2tff(v.x), f2tff(v.y), f2tff(v.z), f2tff(v.w));
    }
}

// ---------------------------------------------------------------------------
// tf32 GEMM + bias, cp.async double-buffered. Inputs pre-rounded to tf32.
// Y = round_tf32((X@W + b) * oscale). 128x128x32 tile, 8 warps (2m x 4n).
// As[m][k] stride 36 ; Bs[k][n] stride 136 (conflict-free fragment LDS).
// blockIdx.z fuses two problems (K and V projections).
// ---------------------------------------------------------------------------
__device__ __forceinline__ void gemm_stage(
    unsigned sA, unsigned sB, const float* __restrict__ X, const float* __restrict__ W,
    int Kdim, int N, int bm, int bn, int k0, int tid)
{
    #pragma unroll
    for (int it = 0; it < 4; it++) {
        int f = tid + it * 256;
        int m  = f >> 3;
        int kq = (f & 7) * 4;
        CP16(sA + (m * 36 + kq) * 4, X + (size_t)(bm + m) * Kdim + k0 + kq);
        int kk = f >> 5;
        int nq = (f & 31) * 4;
        CP16(sB + (kk * 136 + nq) * 4, W + (size_t)(k0 + kk) * N + bn + nq);
    }
}

__global__ __launch_bounds__(256, 2) void gemm_tf32(
    const float* __restrict__ X,
    const float* __restrict__ W0, const float* __restrict__ b0, float* __restrict__ Y0,
    const float* __restrict__ W1, const float* __restrict__ b1, float* __restrict__ Y1,
    int M, int N, int Kdim, float oscale)
{
    const float* __restrict__ W  = blockIdx.z ? W1 : W0;
    const float* __restrict__ bi = blockIdx.z ? b1 : b0;
    float*       __restrict__ Y  = blockIdx.z ? Y1 : Y0;

    extern __shared__ unsigned smg[];   // [2][4608 + 4352]
    const int tid  = threadIdx.x;
    const int lane = tid & 31;
    const int wid  = tid >> 5;
    const int wm   = wid & 1;
    const int wn   = wid >> 1;
    const int lr   = lane >> 2;
    const int lc   = lane & 3;
    const int bm = blockIdx.y * 128;
    const int bn = blockIdx.x * 128;

    unsigned sbase = (unsigned)__cvta_generic_to_shared(smg);

    float acc[4][4][4];
    #pragma unroll
    for (int i = 0; i < 4; i++)
        #pragma unroll
        for (int j = 0; j < 4; j++)
            #pragma unroll
            for (int k = 0; k < 4; k++) acc[i][j][k] = 0.f;

    const int nK = Kdim / 32;
    gemm_stage(sbase, sbase + 4608 * 4, X, W, Kdim, N, bm, bn, 0, tid);
    CPCOMMIT();

    for (int i = 0; i < nK; i++) {
        CPWAIT(0);
        __syncthreads();
        if (i + 1 < nK) {
            unsigned boff = ((i + 1) & 1) * 8960 * 4;
            gemm_stage(sbase + boff, sbase + boff + 4608 * 4,
                       X, W, Kdim, N, bm, bn, (i + 1) * 32, tid);
            CPCOMMIT();
        }
        const unsigned* As = smg + (i & 1) * 8960;
        const unsigned* Bs = As + 4608;

        #pragma unroll
        for (int s = 0; s < 4; s++) {
            const int c = s * 8 + lc;
            unsigned af[4][4], bf[4][2];
            #pragma unroll
            for (int mt = 0; mt < 4; mt++) {
                int r = wm * 64 + mt * 16 + lr;
                af[mt][0] = As[r * 36 + c];
                af[mt][1] = As[(r + 8) * 36 + c];
                af[mt][2] = As[r * 36 + c + 4];
                af[mt][3] = As[(r + 8) * 36 + c + 4];
            }
            #pragma unroll
            for (int nt = 0; nt < 4; nt++) {
                int n = wn * 32 + nt * 8 + lr;
                bf[nt][0] = Bs[c * 136 + n];
                bf[nt][1] = Bs[(c + 4) * 136 + n];
            }
            #pragma unroll
            for (int mt = 0; mt < 4; mt++)
                #pragma unroll
                for (int nt = 0; nt < 4; nt++)
                    mma_tf32(acc[mt][nt], af[mt], bf[nt]);
        }
    }

    #pragma unroll
    for (int mt = 0; mt < 4; mt++) {
        int r = bm + wm * 64 + mt * 16 + lr;
        #pragma unroll
        for (int nt = 0; nt < 4; nt++) {
            int cc = bn + wn * 32 + nt * 8 + 2 * lc;
            float bv0 = bi[cc], bv1 = bi[cc + 1];
            *(float2*)(Y + (size_t)r * N + cc) = make_float2(
                f2tff((acc[mt][nt][0] + bv0) * oscale),
                f2tff((acc[mt][nt][1] + bv1) * oscale));
            *(float2*)(Y + (size_t)(r + 8) * N + cc) = make_float2(
                f2tff((acc[mt][nt][2] + bv0) * oscale),
                f2tff((acc[mt][nt][3] + bv1) * oscale));
        }
    }
}

// ---------------------------------------------------------------------------
// tf32 flash attention, warp-private softmax, cp.async pipelined.
// CTA = 128 q-rows, 8 warps x 16 rows each; 64-key tiles; K double-buffered.
// SMEM floats: Qs[128][132] | Ks[2][64][132] | Vs[64][136] | Ps[128][68]
//   = 51200 floats = 204800 B.
// All fragment LDS patterns bank-conflict-free (pad strides 132/136/68).
// ---------------------------------------------------------------------------
#define ATTN_SMEM_BYTES (51200 * 4)

__global__ __launch_bounds__(256) void attn_tf32(
    const float* __restrict__ Q, const float* __restrict__ K,
    const float* __restrict__ V, float* __restrict__ O)
{
    extern __shared__ float sm[];
    const unsigned* Qs = (const unsigned*)sm;            // 128*132
    float* Ksf = sm + 16896;                              // 2 * 64*132
    const unsigned* Vs = (const unsigned*)(sm + 33792);  // 64*136
    unsigned* Ps = (unsigned*)(sm + 42496);              // 128*68

    const int tid  = threadIdx.x;
    const int lane = tid & 31;
    const int wid  = tid >> 5;
    const int lr = lane >> 2;
    const int lc = lane & 3;
    const int r0 = 16 * wid + lr;
    const int q0 = blockIdx.x * 128;
    const int h  = blockIdx.y;
    const int b  = blockIdx.z;
    const int g  = h & (HKV - 1);

    const float* Qb = Q + (size_t)b * SS * DD  + (size_t)h * HD;
    const float* Kb = K + (size_t)b * SS * KVD + (size_t)g * HD;
    const float* Vb = V + (size_t)b * SS * KVD + (size_t)g * HD;

    unsigned sbase = (unsigned)__cvta_generic_to_shared(sm);
    const unsigned sK = sbase + 16896 * 4;
    const unsigned sV = sbase + 33792 * 4;

    // Prologue: Q tile + K(0) in one async group
    #pragma unroll
    for (int it = 0; it < 16; it++) {
        int f = tid + it * 256;
        int q  = f >> 5;
        int dq = (f & 31) * 4;
        CP16(sbase + (q * 132 + dq) * 4, Qb + (size_t)(q0 + q) * DD + dq);
    }
    #pragma unroll
    for (int it = 0; it < 8; it++) {
        int f = tid + it * 256;
        int key = f >> 5;
        int dq  = (f & 31) * 4;
        CP16(sK + (key * 132 + dq) * 4, Kb + (size_t)key * KVD + dq);
    }
    CPCOMMIT();

    float o[16][4];
    #pragma unroll
    for (int nt = 0; nt < 16; nt++)
        #pragma unroll
        for (int k = 0; k < 4; k++) o[nt][k] = 0.f;
    float rm0 = -INFINITY, rm1 = -INFINITY, rl0 = 0.f, rl1 = 0.f;

    for (int kt = 0; kt < NTILE; kt++) {
        CPWAIT(0);
        __syncthreads();

        // Async V(kt) (own group), then prefetch K(kt+1) (own group)
        #pragma unroll
        for (int it = 0; it < 8; it++) {
            int f = tid + it * 256;
            int key = f >> 5;
            int dq  = (f & 31) * 4;
            CP16(sV + (key * 136 + dq) * 4,
                 Vb + (size_t)(kt * 64 + key) * KVD + dq);
        }
        CPCOMMIT();
        const bool more = (kt + 1 < NTILE);
        if (more) {
            unsigned sKn = sK + ((kt + 1) & 1) * (8448 * 4);
            #pragma unroll
            for (int it = 0; it < 8; it++) {
                int f = tid + it * 256;
                int key = f >> 5;
                int dq  = (f & 31) * 4;
                CP16(sKn + (key * 132 + dq) * 4,
                     Kb + (size_t)((kt + 1) * 64 + key) * KVD + dq);
            }
            CPCOMMIT();
        }

        // S = Q K^T for this warp's 16 rows x 64 keys
        const unsigned* Kst = (const unsigned*)(Ksf + (kt & 1) * 8448);
        float sacc[8][4];
        #pragma unroll
        for (int nt = 0; nt < 8; nt++)
            #pragma unroll
            for (int k = 0; k < 4; k++) sacc[nt][k] = 0.f;

        #pragma unroll
        for (int st = 0; st < 16; st++) {
            const int c = st * 8 + lc;
            unsigned af[4];
            af[0] = Qs[r0 * 132 + c];
            af[1] = Qs[(r0 + 8) * 132 + c];
            af[2] = Qs[r0 * 132 + c + 4];
            af[3] = Qs[(r0 + 8) * 132 + c + 4];
            #pragma unroll
            for (int nt = 0; nt < 8; nt++) {
                int n = 8 * nt + lr;
                unsigned bf[2] = { Kst[n * 132 + c], Kst[n * 132 + c + 4] };
                mma_tf32(sacc[nt], af, bf);
            }
        }

        // Warp-private online softmax (rows r0, r0+8)
        float m0 = sacc[0][0], m1 = sacc[0][2];
        #pragma unroll
        for (int nt = 0; nt < 8; nt++) {
            m0 = fmaxf(m0, fmaxf(sacc[nt][0], sacc[nt][1]));
            m1 = fmaxf(m1, fmaxf(sacc[nt][2], sacc[nt][3]));
        }
        m0 = fmaxf(m0, __shfl_xor_sync(0xffffffffu, m0, 1));
        m0 = fmaxf(m0, __shfl_xor_sync(0xffffffffu, m0, 2));
        m1 = fmaxf(m1, __shfl_xor_sync(0xffffffffu, m1, 1));
        m1 = fmaxf(m1, __shfl_xor_sync(0xffffffffu, m1, 2));
        float mn0 = fmaxf(rm0, m0), mn1 = fmaxf(rm1, m1);
        float al0 = __expf(rm0 - mn0), al1 = __expf(rm1 - mn1);
        float sum0 = 0.f, sum1 = 0.f;
        #pragma unroll
        for (int nt = 0; nt < 8; nt++) {
            float p0 = __expf(sacc[nt][0] - mn0);
            float p1 = __expf(sacc[nt][1] - mn0);
            float p2 = __expf(sacc[nt][2] - mn1);
            float p3 = __expf(sacc[nt][3] - mn1);
            sum0 += p0 + p1;
            sum1 += p2 + p3;
            int cc = 8 * nt + 2 * lc;
            *(uint2*)&Ps[r0 * 68 + cc]       = make_uint2(f2tf(p0), f2tf(p1));
            *(uint2*)&Ps[(r0 + 8) * 68 + cc] = make_uint2(f2tf(p2), f2tf(p3));
        }
        sum0 += __shfl_xor_sync(0xffffffffu, sum0, 1);
        sum0 += __shfl_xor_sync(0xffffffffu, sum0, 2);
        sum1 += __shfl_xor_sync(0xffffffffu, sum1, 1);
        sum1 += __shfl_xor_sync(0xffffffffu, sum1, 2);
        rl0 = rl0 * al0 + sum0;  rm0 = mn0;
        rl1 = rl1 * al1 + sum1;  rm1 = mn1;
        #pragma unroll
        for (int nt = 0; nt < 16; nt++) {
            o[nt][0] *= al0;  o[nt][1] *= al0;
            o[nt][2] *= al1;  o[nt][3] *= al1;
        }
        __syncwarp();

        // V(kt) must be complete in all threads before PV
        if (more) { CPWAIT(1); } else { CPWAIT(0); }
        __syncthreads();

        // O += P V (16 rows x 128 hd cols per warp)
        #pragma unroll
        for (int st = 0; st < 8; st++) {
            const int kk = st * 8 + lc;
            unsigned af[4];
            af[0] = Ps[r0 * 68 + kk];
            af[1] = Ps[(r0 + 8) * 68 + kk];
            af[2] = Ps[r0 * 68 + kk + 4];
            af[3] = Ps[(r0 + 8) * 68 + kk + 4];
            #pragma unroll
            for (int nt = 0; nt < 16; nt++) {
                int n = 8 * nt + lr;
                unsigned bf[2] = { Vs[kk * 136 + n], Vs[(kk + 4) * 136 + n] };
                mma_tf32(o[nt], af, bf);
            }
        }
    }

    // Epilogue
    float* Ob = O + (size_t)b * SS * DD + (size_t)h * HD;
    float inv0 = 1.f / rl0, inv1 = 1.f / rl1;
    #pragma unroll
    for (int nt = 0; nt < 16; nt++) {
        int cc = 8 * nt + 2 * lc;
        *(float2*)(Ob + (size_t)(q0 + r0) * DD + cc) =
            make_float2(o[nt][0] * inv0, o[nt][1] * inv0);
        *(float2*)(Ob + (size_t)(q0 + r0 + 8) * DD + cc) =
            make_float2(o[nt][2] * inv1, o[nt][3] * inv1);
    }
}

// ---------------------------------------------------------------------------
extern "C" void kernel_launch(void* const* d_in, const int* in_sizes, int n_in,
                              void* d_out, int out_size)
{
    (void)in_sizes; (void)n_in; (void)out_size;
    const float* H  = (const float*)d_in[0];
    const float* Wq = (const float*)d_in[1];
    const float* bq = (const float*)d_in[2];
    const float* Wk = (const float*)d_in[3];
    const float* bk = (const float*)d_in[4];
    const float* Wv = (const float*)d_in[5];
    const float* bv = (const float*)d_in[6];
    float* out = (float*)d_out;

    float *Qp, *Kp, *Vp, *Hp, *Wqp, *Wkp, *Wvp;
    cudaGetSymbolAddress((void**)&Qp,  g_Q);
    cudaGetSymbolAddress((void**)&Kp,  g_K);
    cudaGetSymbolAddress((void**)&Vp,  g_V);
    cudaGetSymbolAddress((void**)&Hp,  g_H);
    cudaGetSymbolAddress((void**)&Wqp, g_Wq);
    cudaGetSymbolAddress((void**)&Wkp, g_Wk);
    cudaGetSymbolAddress((void**)&Wvp, g_Wv);

    // Pre-round inputs to tf32-representable fp32
    int nb = 148 * 8;
    cvt_tf32<<<nb, 256>>>(Hp,  H,  (int)((size_t)MM * DD / 4));
    cvt_tf32<<<nb, 256>>>(Wqp, Wq, (int)((size_t)DD * DD / 4));
    cvt_tf32<<<nb, 256>>>(Wkp, Wk, (int)((size_t)DD * KVD / 4));
    cvt_tf32<<<nb, 256>>>(Wvp, Wv, (int)((size_t)DD * KVD / 4));

    const float scale = 0.08838834764831845f;  // 1/sqrt(128)
    cudaFuncSetAttribute(gemm_tf32,
                         cudaFuncAttributeMaxDynamicSharedMemorySize, 71680);
    dim3 blk(256);
    // Q projection (scale folded into epilogue)
    gemm_tf32<<<dim3(DD / 128, MM / 128, 1), blk, 71680>>>(
        Hp, Wqp, bq, Qp, Wqp, bq, Qp, MM, DD, DD, scale);
    // K and V projections fused via z
    gemm_tf32<<<dim3(KVD / 128, MM / 128, 2), blk, 71680>>>(
        Hp, Wkp, bk, Kp, Wvp, bv, Vp, MM, KVD, DD, 1.0f);

    cudaFuncSetAttribute(attn_tf32,
                         cudaFuncAttributeMaxDynamicSharedMemorySize, ATTN_SMEM_BYTES);
    attn_tf32<<<dim3(SS / 128, HQ, BB), blk, ATTN_SMEM_BYTES>>>(Qp, Kp, Vp, out);
}

// round 4
// speedup vs baseline: 3.6930x; 1.0958x over previous
#include <cuda_runtime.h>
#include <math.h>

#define BB   2
#define SS   2048
#define DD   2048
#define HQ   16
#define HKV  4
#define HD   128
#define KVD  512
#define MM   (BB*SS)
#define NT   (SS/64)

// Scratch (device globals)
__device__ float g_Q[(size_t)MM * DD];    // [token][d]  d-octets permuted
__device__ float g_K[(size_t)MM * KVD];   // [token][gd] d-octets permuted
__device__ float g_V[(size_t)MM * KVD];   // [token][gd] plain
__device__ float g_Vt[(size_t)BB * KVD * SS]; // [b*512+gd][s] s-octets permuted
__device__ float g_H[(size_t)MM * DD];    // tf32-rounded, k-octets permuted
__device__ float g_Wq[(size_t)DD * DD];   // tf32-rounded, plain
__device__ float g_Wk[(size_t)DD * KVD];
__device__ float g_Wv[(size_t)DD * KVD];

__device__ __forceinline__ unsigned f2tf(float x) {
    unsigned r;
    asm("cvt.rna.tf32.f32 %0, %1;" : "=r"(r) : "f"(x));
    return r;
}
__device__ __forceinline__ float f2tff(float x) { return __uint_as_float(f2tf(x)); }

__device__ __forceinline__ void mma_tf32(float c[4], const unsigned a[4], const unsigned b[2]) {
    asm volatile(
        "mma.sync.aligned.m16n8k8.row.col.f32.tf32.tf32.f32 "
        "{%0,%1,%2,%3},{%4,%5,%6,%7},{%8,%9},{%0,%1,%2,%3};"
        : "+f"(c[0]), "+f"(c[1]), "+f"(c[2]), "+f"(c[3])
        : "r"(a[0]), "r"(a[1]), "r"(a[2]), "r"(a[3]), "r"(b[0]), "r"(b[1]));
}

#define CP16(dst, src) \
    asm volatile("cp.async.cg.shared.global [%0], [%1], 16;" :: "r"(dst), "l"(src))
#define CPCOMMIT() asm volatile("cp.async.commit_group;")
#define CPWAIT(N)  asm volatile("cp.async.wait_group %0;" :: "n"(N))

// ---------------------------------------------------------------------------
// tf32-round a tensor, no permutation (weights).
// ---------------------------------------------------------------------------
__global__ void cvt_tf32(float* __restrict__ dst, const float* __restrict__ src, int n4)
{
    int i = blockIdx.x * blockDim.x + threadIdx.x;
    int stride = gridDim.x * blockDim.x;
    for (; i < n4; i += stride) {
        float4 v = ((const float4*)src)[i];
        ((float4*)dst)[i] = make_float4(f2tff(v.x), f2tff(v.y), f2tff(v.z), f2tff(v.w));
    }
}

// ---------------------------------------------------------------------------
// tf32-round + permute each 8-float octet to [0,4,1,5,2,6,3,7] (H / activations).
// ---------------------------------------------------------------------------
__global__ void cvt_tf32_perm(float* __restrict__ dst, const float* __restrict__ src, int n8)
{
    int i = blockIdx.x * blockDim.x + threadIdx.x;
    int stride = gridDim.x * blockDim.x;
    for (; i < n8; i += stride) {
        float4 a = ((const float4*)src)[2 * i];
        float4 b = ((const float4*)src)[2 * i + 1];
        ((float4*)dst)[2 * i] =
            make_float4(f2tff(a.x), f2tff(b.x), f2tff(a.y), f2tff(b.y));
        ((float4*)dst)[2 * i + 1] =
            make_float4(f2tff(a.z), f2tff(b.z), f2tff(a.w), f2tff(b.w));
    }
}

// ---------------------------------------------------------------------------
// Transpose V[b][s][gd] -> Vt[b*512+gd][s], s-octets permuted. (V already tf32.)
// ---------------------------------------------------------------------------
__global__ void transpose_v(float* __restrict__ Vt, const float* __restrict__ V)
{
    __shared__ float t[32][33];
    const int s0 = blockIdx.x * 32, gd0 = blockIdx.y * 32, b = blockIdx.z;
    #pragma unroll
    for (int i = 0; i < 4; i++) {
        int row = threadIdx.y + i * 8;
        t[row][threadIdx.x] =
            V[((size_t)b * SS + s0 + row) * KVD + gd0 + threadIdx.x];
    }
    __syncthreads();
    const int j = threadIdx.x;
    const int ssrc = (j & 24) + ((j & 1) ? 4 + ((j & 7) >> 1) : ((j & 7) >> 1));
    #pragma unroll
    for (int i = 0; i < 4; i++) {
        int gdl = threadIdx.y + i * 8;
        Vt[((size_t)b * KVD + gd0 + gdl) * SS + s0 + j] = t[ssrc][gdl];
    }
}

// ---------------------------------------------------------------------------
// tf32 GEMM + bias, cp.async double-buffered, X k-octets pre-permuted.
// Y = round_tf32((X@W + b)*oscale); output d-octets permuted if perm flag.
// As[m][k] stride 40 (LDS.64 a-frags conflict-free); Bs[k][n] stride 136.
// ---------------------------------------------------------------------------
#define GA 5120
#define GB 4352
#define GBUF (GA + GB)

__device__ __forceinline__ void gemm_stage(
    unsigned sA, unsigned sB, const float* __restrict__ X, const float* __restrict__ W,
    int Kdim, int N, int bm, int bn, int k0, int tid)
{
    #pragma unroll
    for (int it = 0; it < 4; it++) {
        int f = tid + it * 256;
        int m  = f >> 3;
        int kq = (f & 7) * 4;
        CP16(sA + (m * 40 + kq) * 4, X + (size_t)(bm + m) * Kdim + k0 + kq);
        int kk = f >> 5;
        int nq = (f & 31) * 4;
        CP16(sB + (kk * 136 + nq) * 4, W + (size_t)(k0 + kk) * N + bn + nq);
    }
}

__global__ __launch_bounds__(256, 2) void gemm_tf32(
    const float* __restrict__ X,
    const float* __restrict__ W0, const float* __restrict__ b0, float* __restrict__ Y0,
    const float* __restrict__ W1, const float* __restrict__ b1, float* __restrict__ Y1,
    int M, int N, int Kdim, float oscale, int perm0, int perm1)
{
    const float* __restrict__ W  = blockIdx.z ? W1 : W0;
    const float* __restrict__ bi = blockIdx.z ? b1 : b0;
    float*       __restrict__ Y  = blockIdx.z ? Y1 : Y0;
    const int permv = blockIdx.z ? perm1 : perm0;

    extern __shared__ unsigned smg[];
    const int tid  = threadIdx.x;
    const int lane = tid & 31;
    const int wid  = tid >> 5;
    const int wm   = wid & 1;
    const int wn   = wid >> 1;
    const int lr   = lane >> 2;
    const int lc   = lane & 3;
    const int bm = blockIdx.y * 128;
    const int bn = blockIdx.x * 128;

    unsigned sbase = (unsigned)__cvta_generic_to_shared(smg);

    float acc[4][4][4];
    #pragma unroll
    for (int i = 0; i < 4; i++)
        #pragma unroll
        for (int j = 0; j < 4; j++)
            #pragma unroll
            for (int k = 0; k < 4; k++) acc[i][j][k] = 0.f;

    const int nK = Kdim / 32;
    gemm_stage(sbase, sbase + GA * 4, X, W, Kdim, N, bm, bn, 0, tid);
    CPCOMMIT();

    for (int i = 0; i < nK; i++) {
        CPWAIT(0);
        __syncthreads();
        if (i + 1 < nK) {
            unsigned boff = ((i + 1) & 1) * GBUF * 4;
            gemm_stage(sbase + boff, sbase + boff + GA * 4,
                       X, W, Kdim, N, bm, bn, (i + 1) * 32, tid);
            CPCOMMIT();
        }
        const unsigned* As = smg + (i & 1) * GBUF;
        const unsigned* Bs = As + GA;

        #pragma unroll
        for (int s = 0; s < 4; s++) {
            const int c = s * 8 + lc;     // original k index for B rows
            unsigned af[4][4], bf[4][2];
            #pragma unroll
            for (int mt = 0; mt < 4; mt++) {
                int r = wm * 64 + mt * 16 + lr;
                uint2 u1 = *(const uint2*)&As[r * 40 + s * 8 + 2 * lc];
                uint2 u2 = *(const uint2*)&As[(r + 8) * 40 + s * 8 + 2 * lc];
                af[mt][0] = u1.x; af[mt][1] = u2.x;
                af[mt][2] = u1.y; af[mt][3] = u2.y;
            }
            #pragma unroll
            for (int nt = 0; nt < 4; nt++) {
                int n = wn * 32 + nt * 8 + lr;
                bf[nt][0] = Bs[c * 136 + n];
                bf[nt][1] = Bs[(c + 4) * 136 + n];
            }
            #pragma unroll
            for (int mt = 0; mt < 4; mt++)
                #pragma unroll
                for (int nt = 0; nt < 4; nt++)
                    mma_tf32(acc[mt][nt], af[mt], bf[nt]);
        }
    }

    const int p0 = (lc < 2) ? 4 * lc : 4 * lc - 7;       // store pos of col 2lc
    const int p1 = (lc < 2) ? 4 * lc + 2 : 4 * lc - 5;   // store pos of col 2lc+1
    #pragma unroll
    for (int mt = 0; mt < 4; mt++) {
        int r = bm + wm * 64 + mt * 16 + lr;
        #pragma unroll
        for (int nt = 0; nt < 4; nt++) {
            int base = bn + wn * 32 + nt * 8;
            float bv0 = bi[base + 2 * lc], bv1 = bi[base + 2 * lc + 1];
            float v00 = f2tff((acc[mt][nt][0] + bv0) * oscale);
            float v01 = f2tff((acc[mt][nt][1] + bv1) * oscale);
            float v10 = f2tff((acc[mt][nt][2] + bv0) * oscale);
            float v11 = f2tff((acc[mt][nt][3] + bv1) * oscale);
            if (permv) {
                Y[(size_t)r * N + base + p0] = v00;
                Y[(size_t)r * N + base + p1] = v01;
                Y[(size_t)(r + 8) * N + base + p0] = v10;
                Y[(size_t)(r + 8) * N + base + p1] = v11;
            } else {
                *(float2*)(Y + (size_t)r * N + base + 2 * lc) = make_float2(v00, v01);
                *(float2*)(Y + (size_t)(r + 8) * N + base + 2 * lc) = make_float2(v10, v11);
            }
        }
    }
}

// ---------------------------------------------------------------------------
// tf32 flash attention. 128 q-rows/CTA, 8 warps x 16 rows; 64-key tiles.
// Q/K d-octets permuted, Vt[d][s] s-octets permuted -> all frag LDS are .64.
// P stays in registers (d-frag -> a-frag via shuffles). K,Vt double-buffered,
// ONE __syncthreads per key tile.
// SMEM floats: Qs[128][136] | Ks[2][64][136] | Vt[2][128][72] = 53248 (208KiB)
// ---------------------------------------------------------------------------
#define QS_OFF 0
#define KS_OFF 17408
#define VT_OFF 34816
#define ATTN_SMEM_BYTES (53248 * 4)

__global__ __launch_bounds__(256) void attn_tf32(
    const float* __restrict__ Q, const float* __restrict__ K,
    const float* __restrict__ Vt, float* __restrict__ O)
{
    extern __shared__ float sm[];
    const unsigned* Qs = (const unsigned*)sm;

    const int tid  = threadIdx.x;
    const int lane = tid & 31;
    const int wid  = tid >> 5;
    const int lr = lane >> 2;
    const int lc = lane & 3;
    const int r0 = 16 * wid + lr;
    const int q0 = blockIdx.x * 128;
    const int h  = blockIdx.y;
    const int b  = blockIdx.z;
    const int g  = h & (HKV - 1);

    const float* Qb = Q  + (size_t)b * SS * DD  + (size_t)h * HD;
    const float* Kb = K  + (size_t)b * SS * KVD + (size_t)g * HD;
    const float* Vb = Vt + ((size_t)b * KVD + (size_t)g * HD) * SS;

    unsigned sbase = (unsigned)__cvta_generic_to_shared(sm);
    const unsigned sK = sbase + KS_OFF * 4;
    const unsigned sV = sbase + VT_OFF * 4;

    // Prologue: Q + K(0) + Vt(0), one group
    #pragma unroll
    for (int it = 0; it < 16; it++) {
        int f = tid + it * 256;
        int q  = f >> 5;
        int dq = (f & 31) * 4;
        CP16(sbase + (q * 136 + dq) * 4, Qb + (size_t)(q0 + q) * DD + dq);
    }
    #pragma unroll
    for (int it = 0; it < 8; it++) {
        int f = tid + it * 256;
        int key = f >> 5;
        int dq  = (f & 31) * 4;
        CP16(sK + (key * 136 + dq) * 4, Kb + (size_t)key * KVD + dq);
    }
    #pragma unroll
    for (int it = 0; it < 8; it++) {
        int f = tid + it * 256;
        int d  = f >> 4;
        int sq = (f & 15) * 4;
        CP16(sV + (d * 72 + sq) * 4, Vb + (size_t)d * SS + sq);
    }
    CPCOMMIT();

    float o[16][4];
    #pragma unroll
    for (int dt = 0; dt < 16; dt++)
        #pragma unroll
        for (int k = 0; k < 4; k++) o[dt][k] = 0.f;
    float rm0 = -INFINITY, rm1 = -INFINITY, rl0 = 0.f, rl1 = 0.f;

    const int sAsrc = lr * 4 + (lc >> 1);   // shuffle sources for P transform
    const int sBsrc = sAsrc + 2;
    const bool oddc = (lc & 1);

    for (int kt = 0; kt < NT; kt++) {
        CPWAIT(0);
        __syncthreads();     // {K,Vt}(kt) complete; all warps past PV(kt-1)

        if (kt + 1 < NT) {   // prefetch {K,Vt}(kt+1)
            unsigned sKn = sK + ((kt + 1) & 1) * (8704 * 4);
            unsigned sVn = sV + ((kt + 1) & 1) * (9216 * 4);
            #pragma unroll
            for (int it = 0; it < 8; it++) {
                int f = tid + it * 256;
                int key = f >> 5;
                int dq  = (f & 31) * 4;
                CP16(sKn + (key * 136 + dq) * 4,
                     Kb + (size_t)((kt + 1) * 64 + key) * KVD + dq);
            }
            #pragma unroll
            for (int it = 0; it < 8; it++) {
                int f = tid + it * 256;
                int d  = f >> 4;
                int sq = (f & 15) * 4;
                CP16(sVn + (d * 72 + sq) * 4,
                     Vb + (size_t)d * SS + (kt + 1) * 64 + sq);
            }
            CPCOMMIT();
        }

        const unsigned* Kst = (const unsigned*)(sm + KS_OFF + (kt & 1) * 8704);
        const unsigned* Vts = (const unsigned*)(sm + VT_OFF + (kt & 1) * 9216);

        // ---- S = Q K^T (16 rows x 64 keys per warp) ----
        float sacc[8][4];
        #pragma unroll
        for (int nt = 0; nt < 8; nt++)
            #pragma unroll
            for (int k = 0; k < 4; k++) sacc[nt][k] = 0.f;

        #pragma unroll
        for (int st = 0; st < 16; st++) {
            uint2 u1 = *(const uint2*)&Qs[r0 * 136 + st * 8 + 2 * lc];
            uint2 u2 = *(const uint2*)&Qs[(r0 + 8) * 136 + st * 8 + 2 * lc];
            unsigned af[4] = { u1.x, u2.x, u1.y, u2.y };
            #pragma unroll
            for (int nt = 0; nt < 8; nt++) {
                uint2 bu = *(const uint2*)&Kst[(8 * nt + lr) * 136 + st * 8 + 2 * lc];
                unsigned bf[2] = { bu.x, bu.y };
                mma_tf32(sacc[nt], af, bf);
            }
        }

        // ---- warp-private online softmax + P -> a-frags in registers ----
        float m0 = sacc[0][0], m1 = sacc[0][2];
        #pragma unroll
        for (int nt = 0; nt < 8; nt++) {
            m0 = fmaxf(m0, fmaxf(sacc[nt][0], sacc[nt][1]));
            m1 = fmaxf(m1, fmaxf(sacc[nt][2], sacc[nt][3]));
        }
        m0 = fmaxf(m0, __shfl_xor_sync(0xffffffffu, m0, 1));
        m0 = fmaxf(m0, __shfl_xor_sync(0xffffffffu, m0, 2));
        m1 = fmaxf(m1, __shfl_xor_sync(0xffffffffu, m1, 1));
        m1 = fmaxf(m1, __shfl_xor_sync(0xffffffffu, m1, 2));
        float mn0 = fmaxf(rm0, m0), mn1 = fmaxf(rm1, m1);
        float al0 = __expf(rm0 - mn0), al1 = __expf(rm1 - mn1);
        float sum0 = 0.f, sum1 = 0.f;
        unsigned pa[8][4];
        #pragma unroll
        for (int nt = 0; nt < 8; nt++) {
            float f0 = __expf(sacc[nt][0] - mn0);
            float f1 = __expf(sacc[nt][1] - mn0);
            float f2 = __expf(sacc[nt][2] - mn1);
            float f3 = __expf(sacc[nt][3] - mn1);
            sum0 += f0 + f1;
            sum1 += f2 + f3;
            unsigned t0 = f2tf(f0), t1 = f2tf(f1), t2 = f2tf(f2), t3 = f2tf(f3);
            unsigned e0 = __shfl_sync(0xffffffffu, t0, sAsrc);
            unsigned o0 = __shfl_sync(0xffffffffu, t1, sAsrc);
            unsigned e1 = __shfl_sync(0xffffffffu, t2, sAsrc);
            unsigned o1 = __shfl_sync(0xffffffffu, t3, sAsrc);
            unsigned e2 = __shfl_sync(0xffffffffu, t0, sBsrc);
            unsigned o2 = __shfl_sync(0xffffffffu, t1, sBsrc);
            unsigned e3 = __shfl_sync(0xffffffffu, t2, sBsrc);
            unsigned o3 = __shfl_sync(0xffffffffu, t3, sBsrc);
            pa[nt][0] = oddc ? o0 : e0;   // (row lr,   k=lc)
            pa[nt][1] = oddc ? o1 : e1;   // (row lr+8, k=lc)
            pa[nt][2] = oddc ? o2 : e2;   // (row lr,   k=lc+4)
            pa[nt][3] = oddc ? o3 : e3;   // (row lr+8, k=lc+4)
        }
        sum0 += __shfl_xor_sync(0xffffffffu, sum0, 1);
        sum0 += __shfl_xor_sync(0xffffffffu, sum0, 2);
        sum1 += __shfl_xor_sync(0xffffffffu, sum1, 1);
        sum1 += __shfl_xor_sync(0xffffffffu, sum1, 2);
        rl0 = rl0 * al0 + sum0;  rm0 = mn0;
        rl1 = rl1 * al1 + sum1;  rm1 = mn1;
        #pragma unroll
        for (int dt = 0; dt < 16; dt++) {
            o[dt][0] *= al0;  o[dt][1] *= al0;
            o[dt][2] *= al1;  o[dt][3] *= al1;
        }

        // ---- O += P V (16 rows x 128 d per warp) ----
        #pragma unroll
        for (int nt = 0; nt < 8; nt++) {
            #pragma unroll
            for (int dt = 0; dt < 16; dt++) {
                uint2 vu = *(const uint2*)&Vts[(8 * dt + lr) * 72 + nt * 8 + 2 * lc];
                unsigned bf[2] = { vu.x, vu.y };
                mma_tf32(o[dt], pa[nt], bf);
            }
        }
    }

    // Epilogue (standard, unpermuted d)
    float* Ob = O + (size_t)b * SS * DD + (size_t)h * HD;
    float inv0 = 1.f / rl0, inv1 = 1.f / rl1;
    #pragma unroll
    for (int dt = 0; dt < 16; dt++) {
        int cc = 8 * dt + 2 * lc;
        *(float2*)(Ob + (size_t)(q0 + r0) * DD + cc) =
            make_float2(o[dt][0] * inv0, o[dt][1] * inv0);
        *(float2*)(Ob + (size_t)(q0 + r0 + 8) * DD + cc) =
            make_float2(o[dt][2] * inv1, o[dt][3] * inv1);
    }
}

// ---------------------------------------------------------------------------
extern "C" void kernel_launch(void* const* d_in, const int* in_sizes, int n_in,
                              void* d_out, int out_size)
{
    (void)in_sizes; (void)n_in; (void)out_size;
    const float* H  = (const float*)d_in[0];
    const float* Wq = (const float*)d_in[1];
    const float* bq = (const float*)d_in[2];
    const float* Wk = (const float*)d_in[3];
    const float* bk = (const float*)d_in[4];
    const float* Wv = (const float*)d_in[5];
    const float* bv = (const float*)d_in[6];
    float* out = (float*)d_out;

    float *Qp, *Kp, *Vp, *Vtp, *Hp, *Wqp, *Wkp, *Wvp;
    cudaGetSymbolAddress((void**)&Qp,  g_Q);
    cudaGetSymbolAddress((void**)&Kp,  g_K);
    cudaGetSymbolAddress((void**)&Vp,  g_V);
    cudaGetSymbolAddress((void**)&Vtp, g_Vt);
    cudaGetSymbolAddress((void**)&Hp,  g_H);
    cudaGetSymbolAddress((void**)&Wqp, g_Wq);
    cudaGetSymbolAddress((void**)&Wkp, g_Wk);
    cudaGetSymbolAddress((void**)&Wvp, g_Wv);

    int nb = 148 * 8;
    cvt_tf32_perm<<<nb, 256>>>(Hp, H, (int)((size_t)MM * DD / 8));
    cvt_tf32<<<nb, 256>>>(Wqp, Wq, (int)((size_t)DD * DD / 4));
    cvt_tf32<<<nb, 256>>>(Wkp, Wk, (int)((size_t)DD * KVD / 4));
    cvt_tf32<<<nb, 256>>>(Wvp, Wv, (int)((size_t)DD * KVD / 4));

    const float scale = 0.08838834764831845f;  // 1/sqrt(128)
    cudaFuncSetAttribute(gemm_tf32,
                         cudaFuncAttributeMaxDynamicSharedMemorySize, GBUF * 2 * 4);
    dim3 blk(256);
    // Q projection (scale folded, output permuted)
    gemm_tf32<<<dim3(DD / 128, MM / 128, 1), blk, GBUF * 2 * 4>>>(
        Hp, Wqp, bq, Qp, Wqp, bq, Qp, MM, DD, DD, scale, 1, 1);
    // K (permuted) and V (plain) projections fused via z
    gemm_tf32<<<dim3(KVD / 128, MM / 128, 2), blk, GBUF * 2 * 4>>>(
        Hp, Wkp, bk, Kp, Wvp, bv, Vp, MM, KVD, DD, 1.0f, 1, 0);

    // V -> Vt (transposed, s-octet permuted)
    transpose_v<<<dim3(SS / 32, KVD / 32, BB), dim3(32, 8)>>>(Vtp, Vp);

    cudaFuncSetAttribute(attn_tf32,
                         cudaFuncAttributeMaxDynamicSharedMemorySize, ATTN_SMEM_BYTES);
    attn_tf32<<<dim3(SS / 128, HQ, BB), blk, ATTN_SMEM_BYTES>>>(Qp, Kp, Vtp, out);
}

// round 6
// speedup vs baseline: 3.7879x; 1.0257x over previous
#include <cuda_runtime.h>
#include <math.h>

#define BB   2
#define SS   2048
#define DD   2048
#define HQ   16
#define HKV  4
#define HD   128
#define KVD  512
#define MM   (BB*SS)
#define NT   (SS/64)

// Scratch (device globals)
__device__ float g_Q[(size_t)MM * DD];    // [token][d]  d-octets permuted, scaled
__device__ float g_K[(size_t)MM * KVD];   // [token][gd] d-octets permuted
__device__ float g_V[(size_t)MM * KVD];   // [token][gd] plain
__device__ float g_Vt[(size_t)BB * KVD * SS]; // [b*512+gd][s] s-octets permuted
__device__ float g_H[(size_t)MM * DD];    // tf32-rounded, k-octets permuted
__device__ float g_Wq[(size_t)DD * DD];   // [k][n] tf32-rounded
__device__ float g_Wk[(size_t)DD * KVD];
__device__ float g_Wv[(size_t)DD * KVD];

__device__ __forceinline__ unsigned f2tf(float x) {
    unsigned r;
    asm("cvt.rna.tf32.f32 %0, %1;" : "=r"(r) : "f"(x));
    return r;
}
__device__ __forceinline__ float f2tff(float x) { return __uint_as_float(f2tf(x)); }

__device__ __forceinline__ void mma_tf32(float c[4], const unsigned a[4], const unsigned b[2]) {
    asm volatile(
        "mma.sync.aligned.m16n8k8.row.col.f32.tf32.tf32.f32 "
        "{%0,%1,%2,%3},{%4,%5,%6,%7},{%8,%9},{%0,%1,%2,%3};"
        : "+f"(c[0]), "+f"(c[1]), "+f"(c[2]), "+f"(c[3])
        : "r"(a[0]), "r"(a[1]), "r"(a[2]), "r"(a[3]), "r"(b[0]), "r"(b[1]));
}

#define CP16(dst, src) \
    asm volatile("cp.async.cg.shared.global [%0], [%1], 16;" :: "r"(dst), "l"(src))
#define CPCOMMIT() asm volatile("cp.async.commit_group;")
#define CPWAIT(N)  asm volatile("cp.async.wait_group %0;" :: "n"(N))

#define MBAR_INIT(addr, cnt) \
    asm volatile("mbarrier.init.shared.b64 [%0], %1;" :: "r"(addr), "r"(cnt) : "memory")
#define MBAR_ARRIVE(addr) \
    asm volatile("mbarrier.arrive.shared.b64 _, [%0];" :: "r"(addr) : "memory")
#define CPASYNC_MBAR_ARRIVE(addr) \
    asm volatile("cp.async.mbarrier.arrive.noinc.shared.b64 [%0];" :: "r"(addr) : "memory")

#define MBAR_WAIT(addr, par) do { \
    unsigned _m = (addr), _p = (par), _d; \
    asm volatile("{\n\t.reg .pred p;\n\t" \
        "mbarrier.try_wait.parity.acquire.cta.shared::cta.b64 p, [%1], %2;\n\t" \
        "selp.b32 %0, 1, 0, p;\n\t}" : "=r"(_d) : "r"(_m), "r"(_p) : "memory"); \
    if (!_d) { \
        asm volatile("{\n\t.reg .pred P1;\n\t" \
            "WL%=:\n\t" \
            "mbarrier.try_wait.parity.acquire.cta.shared::cta.b64 P1, [%0], %1, 0x989680;\n\t" \
            "@P1 bra.uni WD%=;\n\t" \
            "bra.uni WL%=;\n\t" \
            "WD%=:\n\t}" :: "r"(_m), "r"(_p) : "memory"); \
    } \
} while (0)

// ---------------------------------------------------------------------------
// tf32-round (weights, natural order)
// ---------------------------------------------------------------------------
__global__ void cvt_tf32(float* __restrict__ dst, const float* __restrict__ src, int n4)
{
    int i = blockIdx.x * blockDim.x + threadIdx.x;
    int stride = gridDim.x * blockDim.x;
    for (; i < n4; i += stride) {
        float4 v = ((const float4*)src)[i];
        ((float4*)dst)[i] = make_float4(f2tff(v.x), f2tff(v.y), f2tff(v.z), f2tff(v.w));
    }
}

// ---------------------------------------------------------------------------
// tf32-round + octet permute [0,4,1,5,2,6,3,7]  (H / activations)
// ---------------------------------------------------------------------------
__global__ void cvt_tf32_perm(float* __restrict__ dst, const float* __restrict__ src, int n8)
{
    int i = blockIdx.x * blockDim.x + threadIdx.x;
    int stride = gridDim.x * blockDim.x;
    for (; i < n8; i += stride) {
        float4 a = ((const float4*)src)[2 * i];
        float4 b = ((const float4*)src)[2 * i + 1];
        ((float4*)dst)[2 * i] =
            make_float4(f2tff(a.x), f2tff(b.x), f2tff(a.y), f2tff(b.y));
        ((float4*)dst)[2 * i + 1] =
            make_float4(f2tff(a.z), f2tff(b.z), f2tff(a.w), f2tff(b.w));
    }
}

// ---------------------------------------------------------------------------
// Transpose V[b][s][gd] -> Vt[b*512+gd][s], s-octets permuted.
// ---------------------------------------------------------------------------
__global__ void transpose_v(float* __restrict__ Vt, const float* __restrict__ V)
{
    __shared__ float t[32][33];
    const int s0 = blockIdx.x * 32, gd0 = blockIdx.y * 32, b = blockIdx.z;
    #pragma unroll
    for (int i = 0; i < 4; i++) {
        int row = threadIdx.y + i * 8;
        t[row][threadIdx.x] =
            V[((size_t)b * SS + s0 + row) * KVD + gd0 + threadIdx.x];
    }
    __syncthreads();
    const int j = threadIdx.x;
    const int ssrc = (j & 24) + ((j & 1) ? 4 + ((j & 7) >> 1) : ((j & 7) >> 1));
    #pragma unroll
    for (int i = 0; i < 4; i++) {
        int gdl = threadIdx.y + i * 8;
        Vt[((size_t)b * KVD + gd0 + gdl) * SS + s0 + j] = t[ssrc][gdl];
    }
}

// ---------------------------------------------------------------------------
// tf32 GEMM + bias: Y = X@W + b. CTA tile 128x256x32, 8 warps (2m x 4n),
// 64x64 warp tiles, cp.async double-buffered. X k-octets pre-permuted.
// As[m][k] stride 40 (LDS.64 a-frags); Bs[k][n] stride 264.
// blockIdx.z fuses two (W,b,Y) problems.
// ---------------------------------------------------------------------------
#define GA 5120
#define GB 8448
#define GBUF (GA + GB)
#define GEMM_SMEM_BYTES (GBUF * 2 * 4)

__device__ __forceinline__ void gemm_stage(
    unsigned sA, unsigned sB, const float* __restrict__ X, const float* __restrict__ W,
    int Kdim, int N, int bm, int bn, int k0, int tid)
{
    #pragma unroll
    for (int it = 0; it < 4; it++) {              // A: 128 x 32
        int f = tid + it * 256;
        int m  = f >> 3;
        int kq = (f & 7) * 4;
        CP16(sA + (m * 40 + kq) * 4, X + (size_t)(bm + m) * Kdim + k0 + kq);
    }
    #pragma unroll
    for (int it = 0; it < 8; it++) {              // B: 32 x 256
        int f = tid + it * 256;
        int kk = f >> 6;
        int nq = (f & 63) * 4;
        CP16(sB + (kk * 264 + nq) * 4, W + (size_t)(k0 + kk) * N + bn + nq);
    }
}

__global__ __launch_bounds__(256) void gemm_tf32(
    const float* __restrict__ X,
    const float* __restrict__ W0, const float* __restrict__ b0, float* __restrict__ Y0,
    const float* __restrict__ W1, const float* __restrict__ b1, float* __restrict__ Y1,
    int N, int Kdim, float oscale, int perm0, int perm1)
{
    const float* __restrict__ W  = blockIdx.z ? W1 : W0;
    const float* __restrict__ bi = blockIdx.z ? b1 : b0;
    float*       __restrict__ Y  = blockIdx.z ? Y1 : Y0;
    const int permv = blockIdx.z ? perm1 : perm0;

    extern __shared__ unsigned smg[];
    const int tid  = threadIdx.x;
    const int lane = tid & 31;
    const int wid  = tid >> 5;
    const int wm   = wid >> 2;     // 0..1
    const int wn   = wid & 3;      // 0..3
    const int lr   = lane >> 2;
    const int lc   = lane & 3;
    const int bm = blockIdx.y * 128;
    const int bn = blockIdx.x * 256;

    unsigned sbase = (unsigned)__cvta_generic_to_shared(smg);

    float acc[4][8][4];
    #pragma unroll
    for (int i = 0; i < 4; i++)
        #pragma unroll
        for (int j = 0; j < 8; j++)
            #pragma unroll
            for (int k = 0; k < 4; k++) acc[i][j][k] = 0.f;

    const int nK = Kdim / 32;
    gemm_stage(sbase, sbase + GA * 4, X, W, Kdim, N, bm, bn, 0, tid);
    CPCOMMIT();

    for (int i = 0; i < nK; i++) {
        CPWAIT(0);
        __syncthreads();
        if (i + 1 < nK) {
            unsigned boff = ((i + 1) & 1) * GBUF * 4;
            gemm_stage(sbase + boff, sbase + boff + GA * 4,
                       X, W, Kdim, N, bm, bn, (i + 1) * 32, tid);
            CPCOMMIT();
        }
        const unsigned* As = smg + (i & 1) * GBUF;
        const unsigned* Bs = As + GA;

        #pragma unroll
        for (int s = 0; s < 4; s++) {
            const int c = s * 8 + lc;
            unsigned af[4][4], bf[8][2];
            #pragma unroll
            for (int mt = 0; mt < 4; mt++) {
                int r = wm * 64 + mt * 16 + lr;
                uint2 u1 = *(const uint2*)&As[r * 40 + s * 8 + 2 * lc];
                uint2 u2 = *(const uint2*)&As[(r + 8) * 40 + s * 8 + 2 * lc];
                af[mt][0] = u1.x; af[mt][1] = u2.x;
                af[mt][2] = u1.y; af[mt][3] = u2.y;
            }
            #pragma unroll
            for (int nt = 0; nt < 8; nt++) {
                int n = wn * 64 + nt * 8 + lr;
                bf[nt][0] = Bs[c * 264 + n];
                bf[nt][1] = Bs[(c + 4) * 264 + n];
            }
            #pragma unroll
            for (int mt = 0; mt < 4; mt++)
                #pragma unroll
                for (int nt = 0; nt < 8; nt++)
                    mma_tf32(acc[mt][nt], af[mt], bf[nt]);
        }
        __syncthreads();
    }

    const int p0 = (lc < 2) ? 4 * lc : 4 * lc - 7;
    const int p1 = (lc < 2) ? 4 * lc + 2 : 4 * lc - 5;
    #pragma unroll
    for (int mt = 0; mt < 4; mt++) {
        int r = bm + wm * 64 + mt * 16 + lr;
        #pragma unroll
        for (int nt = 0; nt < 8; nt++) {
            int base = bn + wn * 64 + nt * 8;
            float bv0 = bi[base + 2 * lc], bv1 = bi[base + 2 * lc + 1];
            float v00 = f2tff((acc[mt][nt][0] + bv0) * oscale);
            float v01 = f2tff((acc[mt][nt][1] + bv1) * oscale);
            float v10 = f2tff((acc[mt][nt][2] + bv0) * oscale);
            float v11 = f2tff((acc[mt][nt][3] + bv1) * oscale);
            if (permv) {
                Y[(size_t)r * N + base + p0] = v00;
                Y[(size_t)r * N + base + p1] = v01;
                Y[(size_t)(r + 8) * N + base + p0] = v10;
                Y[(size_t)(r + 8) * N + base + p1] = v11;
            } else {
                *(float2*)(Y + (size_t)r * N + base + 2 * lc) = make_float2(v00, v01);
                *(float2*)(Y + (size_t)(r + 8) * N + base + 2 * lc) = make_float2(v10, v11);
            }
        }
    }
}

// ---------------------------------------------------------------------------
// tf32 flash attention, mbarrier pipelined, Q register-resident.
// 128 q-rows/CTA, 8 warps x 16 rows; 64-key tiles; K/Vt TRIPLE-buffered;
// NO __syncthreads in the main loop: per-slot full (cp.async completion) and
// empty (consumer release) mbarriers let warps skew up to ~2 tiles.
// SMEM floats: K[3][64*136]=26112 | Vt[3][128*72]=27648 | 6 mbarriers.
// Q is staged once through the K region, then lives in registers (64 regs).
// ---------------------------------------------------------------------------
#define KSLOT 8704
#define VSLOT 9216
#define VBASE 26112
#define BARW  53760
#define ATTN_SMEM_BYTES (53776 * 4)

__global__ __launch_bounds__(256) void attn_tf32(
    const float* __restrict__ Q, const float* __restrict__ K,
    const float* __restrict__ Vt, float* __restrict__ O)
{
    extern __shared__ float sm[];

    const int tid  = threadIdx.x;
    const int lane = tid & 31;
    const int wid  = tid >> 5;
    const int lr = lane >> 2;
    const int lc = lane & 3;
    const int r0 = 16 * wid + lr;
    const int q0 = blockIdx.x * 128;
    const int h  = blockIdx.y;
    const int b  = blockIdx.z;
    const int g  = h & (HKV - 1);

    const float* Qb = Q  + (size_t)b * SS * DD  + (size_t)h * HD;
    const float* Kb = K  + (size_t)b * SS * KVD + (size_t)g * HD;
    const float* Vb = Vt + ((size_t)b * KVD + (size_t)g * HD) * SS;

    unsigned sbase = (unsigned)__cvta_generic_to_shared(sm);

    if (tid == 0) {
        #pragma unroll
        for (int s = 0; s < 3; s++) {
            MBAR_INIT(sbase + (BARW + 2 * s) * 4, 256);      // full[s]
            MBAR_INIT(sbase + (BARW + 6 + 2 * s) * 4, 256);  // empty[s]
        }
    }

    // --- Prologue: stage Q through K region, move to registers ---
    #pragma unroll
    for (int it = 0; it < 16; it++) {
        int f = tid + it * 256;
        int q  = f >> 5;
        int dq = (f & 31) * 4;
        CP16(sbase + (q * 136 + dq) * 4, Qb + (size_t)(q0 + q) * DD + dq);
    }
    CPCOMMIT();
    CPWAIT(0);
    __syncthreads();            // Q staged + barriers initialized

    unsigned qa[16][4];
    {
        const unsigned* Qs = (const unsigned*)sm;
        #pragma unroll
        for (int st = 0; st < 16; st++) {
            uint2 u1 = *(const uint2*)&Qs[r0 * 136 + st * 8 + 2 * lc];
            uint2 u2 = *(const uint2*)&Qs[(r0 + 8) * 136 + st * 8 + 2 * lc];
            qa[st][0] = u1.x; qa[st][1] = u2.x;
            qa[st][2] = u1.y; qa[st][3] = u2.y;
        }
    }
    __syncthreads();            // all Q reads done before K slot 0/1 fills

    // --- Fill slots 0 and 1 ---
    #pragma unroll
    for (int s = 0; s < 2; s++) {
        unsigned sKs = sbase + s * KSLOT * 4;
        unsigned sVs = sbase + (VBASE + s * VSLOT) * 4;
        #pragma unroll
        for (int it = 0; it < 8; it++) {
            int f = tid + it * 256;
            int key = f >> 5;
            int dq  = (f & 31) * 4;
            CP16(sKs + (key * 136 + dq) * 4,
                 Kb + (size_t)(s * 64 + key) * KVD + dq);
        }
        #pragma unroll
        for (int it = 0; it < 8; it++) {
            int f = tid + it * 256;
            int d  = f >> 4;
            int sq = (f & 15) * 4;
            CP16(sVs + (d * 72 + sq) * 4, Vb + (size_t)d * SS + s * 64 + sq);
        }
        CPASYNC_MBAR_ARRIVE(sbase + (BARW + 2 * s) * 4);
    }

    float o[16][4];
    #pragma unroll
    for (int dt = 0; dt < 16; dt++)
        #pragma unroll
        for (int k = 0; k < 4; k++) o[dt][k] = 0.f;
    float rm0 = -INFINITY, rm1 = -INFINITY, rl0 = 0.f, rl1 = 0.f;

    const int sAsrc = lr * 4 + (lc >> 1);
    const int sBsrc = sAsrc + 2;
    const bool oddc = (lc & 1);

    #pragma unroll 1
    for (int kt = 0; kt < NT; kt++) {
        // --- producer: fill slot (kt+2)%3 for tile kt+2 ---
        const int fs = kt + 2;
        if (fs < NT) {
            const int slot = fs % 3;
            if (fs >= 3) MBAR_WAIT(sbase + (BARW + 6 + 2 * slot) * 4,
                                   (unsigned)(((fs / 3) - 1) & 1));
            unsigned sKs = sbase + slot * KSLOT * 4;
            unsigned sVs = sbase + (VBASE + slot * VSLOT) * 4;
            #pragma unroll
            for (int it = 0; it < 8; it++) {
                int f = tid + it * 256;
                int key = f >> 5;
                int dq  = (f & 31) * 4;
                CP16(sKs + (key * 136 + dq) * 4,
                     Kb + (size_t)(fs * 64 + key) * KVD + dq);
            }
            #pragma unroll
            for (int it = 0; it < 8; it++) {
                int f = tid + it * 256;
                int d  = f >> 4;
                int sq = (f & 15) * 4;
                CP16(sVs + (d * 72 + sq) * 4, Vb + (size_t)d * SS + fs * 64 + sq);
            }
            CPASYNC_MBAR_ARRIVE(sbase + (BARW + 2 * slot) * 4);
        }

        // --- consumer: wait slot kt%3 full ---
        const int slot = kt % 3;
        MBAR_WAIT(sbase + (BARW + 2 * slot) * 4, (unsigned)((kt / 3) & 1));
        const unsigned* Kst = (const unsigned*)(sm + slot * KSLOT);
        const unsigned* Vts = (const unsigned*)(sm + VBASE + slot * VSLOT);

        // ---- S = Q K^T ----
        float sacc[8][4];
        #pragma unroll
        for (int nt = 0; nt < 8; nt++)
            #pragma unroll
            for (int k = 0; k < 4; k++) sacc[nt][k] = 0.f;

        #pragma unroll
        for (int st = 0; st < 16; st++) {
            #pragma unroll
            for (int nt = 0; nt < 8; nt++) {
                uint2 bu = *(const uint2*)&Kst[(8 * nt + lr) * 136 + st * 8 + 2 * lc];
                unsigned bf[2] = { bu.x, bu.y };
                mma_tf32(sacc[nt], qa[st], bf);
            }
        }

        // ---- warp-private online softmax; P -> a-frags via shuffles ----
        float m0 = sacc[0][0], m1 = sacc[0][2];
        #pragma unroll
        for (int nt = 0; nt < 8; nt++) {
            m0 = fmaxf(m0, fmaxf(sacc[nt][0], sacc[nt][1]));
            m1 = fmaxf(m1, fmaxf(sacc[nt][2], sacc[nt][3]));
        }
        m0 = fmaxf(m0, __shfl_xor_sync(0xffffffffu, m0, 1));
        m0 = fmaxf(m0, __shfl_xor_sync(0xffffffffu, m0, 2));
        m1 = fmaxf(m1, __shfl_xor_sync(0xffffffffu, m1, 1));
        m1 = fmaxf(m1, __shfl_xor_sync(0xffffffffu, m1, 2));
        float mn0 = fmaxf(rm0, m0), mn1 = fmaxf(rm1, m1);
        float al0 = __expf(rm0 - mn0), al1 = __expf(rm1 - mn1);
        float sum0 = 0.f, sum1 = 0.f;
        unsigned pa[8][4];
        #pragma unroll
        for (int nt = 0; nt < 8; nt++) {
            float f0 = __expf(sacc[nt][0] - mn0);
            float f1 = __expf(sacc[nt][1] - mn0);
            float f2 = __expf(sacc[nt][2] - mn1);
            float f3 = __expf(sacc[nt][3] - mn1);
            sum0 += f0 + f1;
            sum1 += f2 + f3;
            unsigned t0 = f2tf(f0), t1 = f2tf(f1), t2 = f2tf(f2), t3 = f2tf(f3);
            unsigned e0 = __shfl_sync(0xffffffffu, t0, sAsrc);
            unsigned o0 = __shfl_sync(0xffffffffu, t1, sAsrc);
            unsigned e1 = __shfl_sync(0xffffffffu, t2, sAsrc);
            unsigned o1 = __shfl_sync(0xffffffffu, t3, sAsrc);
            unsigned e2 = __shfl_sync(0xffffffffu, t0, sBsrc);
            unsigned o2 = __shfl_sync(0xffffffffu, t1, sBsrc);
            unsigned e3 = __shfl_sync(0xffffffffu, t2, sBsrc);
            unsigned o3 = __shfl_sync(0xffffffffu, t3, sBsrc);
            pa[nt][0] = oddc ? o0 : e0;
            pa[nt][1] = oddc ? o1 : e1;
            pa[nt][2] = oddc ? o2 : e2;
            pa[nt][3] = oddc ? o3 : e3;
        }
        sum0 += __shfl_xor_sync(0xffffffffu, sum0, 1);
        sum0 += __shfl_xor_sync(0xffffffffu, sum0, 2);
        sum1 += __shfl_xor_sync(0xffffffffu, sum1, 1);
        sum1 += __shfl_xor_sync(0xffffffffu, sum1, 2);
        rl0 = rl0 * al0 + sum0;  rm0 = mn0;
        rl1 = rl1 * al1 + sum1;  rm1 = mn1;
        #pragma unroll
        for (int dt = 0; dt < 16; dt++) {
            o[dt][0] *= al0;  o[dt][1] *= al0;
            o[dt][2] *= al1;  o[dt][3] *= al1;
        }

        // ---- O += P V ----
        #pragma unroll
        for (int nt = 0; nt < 8; nt++) {
            #pragma unroll
            for (int dt = 0; dt < 16; dt++) {
                uint2 vu = *(const uint2*)&Vts[(8 * dt + lr) * 72 + nt * 8 + 2 * lc];
                unsigned bf[2] = { vu.x, vu.y };
                mma_tf32(o[dt], pa[nt], bf);
            }
        }

        // release slot
        MBAR_ARRIVE(sbase + (BARW + 6 + 2 * slot) * 4);
    }

    // Epilogue
    float* Ob = O + (size_t)b * SS * DD + (size_t)h * HD;
    float inv0 = 1.f / rl0, inv1 = 1.f / rl1;
    #pragma unroll
    for (int dt = 0; dt < 16; dt++) {
        int cc = 8 * dt + 2 * lc;
        *(float2*)(Ob + (size_t)(q0 + r0) * DD + cc) =
            make_float2(o[dt][0] * inv0, o[dt][1] * inv0);
        *(float2*)(Ob + (size_t)(q0 + r0 + 8) * DD + cc) =
            make_float2(o[dt][2] * inv1, o[dt][3] * inv1);
    }
}

// ---------------------------------------------------------------------------
extern "C" void kernel_launch(void* const* d_in, const int* in_sizes, int n_in,
                              void* d_out, int out_size)
{
    (void)in_sizes; (void)n_in; (void)out_size;
    const float* H  = (const float*)d_in[0];
    const float* Wq = (const float*)d_in[1];
    const float* bq = (const float*)d_in[2];
    const float* Wk = (const float*)d_in[3];
    const float* bk = (const float*)d_in[4];
    const float* Wv = (const float*)d_in[5];
    const float* bv = (const float*)d_in[6];
    float* out = (float*)d_out;

    float *Qp, *Kp, *Vp, *Vtp, *Hp, *Wqp, *Wkp, *Wvp;
    cudaGetSymbolAddress((void**)&Qp,  g_Q);
    cudaGetSymbolAddress((void**)&Kp,  g_K);
    cudaGetSymbolAddress((void**)&Vp,  g_V);
    cudaGetSymbolAddress((void**)&Vtp, g_Vt);
    cudaGetSymbolAddress((void**)&Hp,  g_H);
    cudaGetSymbolAddress((void**)&Wqp, g_Wq);
    cudaGetSymbolAddress((void**)&Wkp, g_Wk);
    cudaGetSymbolAddress((void**)&Wvp, g_Wv);

    int nb = 148 * 8;
    cvt_tf32_perm<<<nb, 256>>>(Hp, H, (int)((size_t)MM * DD / 8));
    cvt_tf32<<<nb, 256>>>(Wqp, Wq, (int)((size_t)DD * DD / 4));
    cvt_tf32<<<nb, 256>>>(Wkp, Wk, (int)((size_t)DD * KVD / 4));
    cvt_tf32<<<nb, 256>>>(Wvp, Wv, (int)((size_t)DD * KVD / 4));

    const float scale = 0.08838834764831845f;  // 1/sqrt(128)
    cudaFuncSetAttribute(gemm_tf32,
                         cudaFuncAttributeMaxDynamicSharedMemorySize, GEMM_SMEM_BYTES);
    // Q projection: N=2048, scale folded, output octet-permuted
    gemm_tf32<<<dim3(DD / 256, MM / 128, 1), 256, GEMM_SMEM_BYTES>>>(
        Hp, Wqp, bq, Qp, Wqp, bq, Qp, DD, DD, scale, 1, 1);
    // K (permuted) and V (plain) projections fused via z: N=512
    gemm_tf32<<<dim3(KVD / 256, MM / 128, 2), 256, GEMM_SMEM_BYTES>>>(
        Hp, Wkp, bk, Kp, Wvp, bv, Vp, KVD, DD, 1.0f, 1, 0);

    transpose_v<<<dim3(SS / 32, KVD / 32, BB), dim3(32, 8)>>>(Vtp, Vp);

    cudaFuncSetAttribute(attn_tf32,
                         cudaFuncAttributeMaxDynamicSharedMemorySize, ATTN_SMEM_BYTES);
    attn_tf32<<<dim3(SS / 128, HQ, BB), 256, ATTN_SMEM_BYTES>>>(Qp, Kp, Vtp, out);
}